// round 2
// baseline (speedup 1.0000x reference)
#include <cuda_runtime.h>
#include <cstdint>

// ---------------- problem constants ----------------
#define NB      256     // bases
#define KD      768     // patch dim (3*16*16)
#define NIMG    64
#define NROW    27      // patch rows (= cols) per image
#define NPATIMG 729     // 27*27
#define ITERS   50

typedef unsigned long long u64;

// ---------------- device scratch (static: allocation-free) ----------------
__device__ float        g_gram[NB * NB];                 // D D^T - I
__device__ float        g_colsum[NB];                    // row sums of D
__device__ float        g_b[(size_t)NIMG * NPATIMG * NB];// feedforward drive (47.8 MB)
__device__ unsigned int g_maxbits[NIMG * NB];            // monotone-encoded running max

// ---------------- helpers ----------------
__device__ __forceinline__ void fma2(u64 &acc, u64 a, u64 b) {
    asm("fma.rn.f32x2 %0, %1, %2, %0;" : "+l"(acc) : "l"(a), "l"(b));
}
__device__ __forceinline__ float hsum2(u64 v) {
    unsigned int lo, hi;
    asm("mov.b64 {%0,%1}, %2;" : "=r"(lo), "=r"(hi) : "l"(v));
    return __uint_as_float(lo) + __uint_as_float(hi);
}
__device__ __forceinline__ float softshrink(float x) {
    return copysignf(fmaxf(fabsf(x) - 0.5f, 0.0f), x);
}
// monotone float->uint encoding so unsigned atomicMax == float max
__device__ __forceinline__ unsigned int enc_f(float x) {
    unsigned int b = __float_as_uint(x);
    return (b & 0x80000000u) ? ~b : (b | 0x80000000u);
}

// ---------------- K0: init running max ----------------
__global__ void init_kernel() {
    g_maxbits[blockIdx.x * NB + threadIdx.x] = 0u;  // key 0 < enc of any real float
}

// ---------------- K1: gram = D D^T - I, colsum ----------------
__global__ void __launch_bounds__(256) gram_kernel(const float* __restrict__ D) {
    __shared__ float di[KD];
    __shared__ float red[256];
    const int i = blockIdx.x;
    const int t = threadIdx.x;

    // stage row i
    const float4* Di4 = (const float4*)(D + (size_t)i * KD);
    for (int q = t; q < KD / 4; q += 256) ((float4*)di)[q] = Di4[q];
    __syncthreads();

    // dot(row i, row t)
    const float4* Dj4 = (const float4*)(D + (size_t)t * KD);
    float acc = 0.f;
    #pragma unroll 4
    for (int q = 0; q < KD / 4; q++) {
        float4 v = __ldg(&Dj4[q]);
        acc += v.x * di[4*q] + v.y * di[4*q+1] + v.z * di[4*q+2] + v.w * di[4*q+3];
    }
    g_gram[i * NB + t] = acc - ((i == t) ? 1.0f : 0.0f);

    // colsum of row i (block reduce)
    red[t] = di[t] + di[t + 256] + di[t + 512];
    __syncthreads();
    for (int o = 128; o > 0; o >>= 1) {
        if (t < o) red[t] += red[t + o];
        __syncthreads();
    }
    if (t == 0) g_colsum[i] = red[0];
}

// ---------------- K2: patch strip -> b = std_fold(raw @ D^T) ----------------
// one CTA per (image, patch-row). smem: strip[3*16*224] + dt2[32][256] f32x2 D tile.
#define K2_STRIP_F   (3 * 16 * 224)              // 10752 floats
#define K2_DT2_OFF   43264                       // byte offset (strip 43008 + stats, aligned)
#define K2_SMEM      (K2_DT2_OFF + 32 * 256 * 8) // 108800 B

__global__ void __launch_bounds__(256, 1) b_kernel(const float* __restrict__ img,
                                                   const float* __restrict__ D) {
    extern __shared__ char smraw[];
    float* strip  = (float*)smraw;                       // [48 rows][224]
    float* mean_s = strip + K2_STRIP_F;                  // [28]
    float* inv_s  = mean_s + 28;                         // [28]
    u64*   dt2    = (u64*)(smraw + K2_DT2_OFF);          // [32 dpairs][256 n]

    const int blk = blockIdx.x;
    const int im  = blk / NROW;
    const int py  = blk - im * NROW;
    const int t   = threadIdx.x;
    const int pt  = t >> 6;     // 0..3  (patch group)
    const int nt  = t & 63;     // 0..63 (basis lane)

    // ---- load strip: rows y in [8*py, 8*py+16) for all 3 channels ----
    const float* ibase = img + (size_t)im * 3 * 224 * 224 + (size_t)(py * 8) * 224;
    for (int e = t; e < K2_STRIP_F; e += 256) {
        int c   = e / 3584;             // 16*224
        int rem = e - c * 3584;         // ph*224 + x
        strip[e] = ibase[(size_t)c * 224 * 224 + rem];
    }
    __syncthreads();

    // ---- per-patch mean / unbiased std (8 lanes per patch, all lanes active) ----
    {
        int p  = t >> 3; if (p > 26) p = 26;   // clamp: lanes 216..255 redundant
        int l8 = t & 7;
        float sm = 0.f, sq = 0.f;
        int xoff = p * 8;
        for (int d = l8; d < KD; d += 8) {
            int rowi = d >> 4;          // c*16+ph
            int pw   = d & 15;
            float v = strip[rowi * 224 + xoff + pw];
            sm += v; sq += v * v;
        }
        #pragma unroll
        for (int o = 4; o > 0; o >>= 1) {
            sm += __shfl_down_sync(0xffffffffu, sm, o);
            sq += __shfl_down_sync(0xffffffffu, sq, o);
        }
        if (l8 == 0 && (t >> 3) < 27) {
            float m   = sm * (1.0f / 768.0f);
            float var = fmaxf(sq - sm * sm * (1.0f / 768.0f), 0.0f) * (1.0f / 767.0f);
            mean_s[p] = m;
            inv_s[p]  = 1.0f / (sqrtf(var) + 1e-8f);
        }
    }

    // ---- GEMM: raw[p][n] = sum_d strip(p,d) * D[n][d], f32x2 over d-pairs ----
    u64 acc[4][7];
    #pragma unroll
    for (int i = 0; i < 4; i++)
        #pragma unroll
        for (int k = 0; k < 7; k++) acc[i][k] = 0ull;

    const u64* Dg = (const u64*)D;   // row = 384 u64
    #pragma unroll 1
    for (int d0 = 0; d0 < KD; d0 += 64) {
        __syncthreads();
        #pragma unroll
        for (int r = 0; r < 32; r++) {
            int n = r * 8 + (t >> 5);
            dt2[(size_t)(t & 31) * NB + n] = __ldg(&Dg[(size_t)n * 384 + (d0 >> 1) + (t & 31)]);
        }
        __syncthreads();

        #pragma unroll 4
        for (int q = 0; q < 32; q++) {
            int d    = d0 + 2 * q;
            int rowi = d >> 4;
            int pw   = d & 15;
            const float* srow = strip + rowi * 224 + pw;
            u64 av[7];
            #pragma unroll
            for (int k = 0; k < 7; k++) {
                int p  = pt * 7 + k;
                int px = (p > 26) ? 26 : p;          // dummy patch 27 clamps
                av[k] = *(const u64*)(srow + px * 8);
            }
            #pragma unroll
            for (int i = 0; i < 4; i++) {
                u64 g = dt2[(size_t)q * NB + nt + 64 * i];
                #pragma unroll
                for (int k = 0; k < 7; k++) fma2(acc[i][k], av[k], g);
            }
        }
    }

    // ---- epilogue: fold standardization, write b ----
    float* bout = g_b + (size_t)(im * NPATIMG + py * NROW) * NB;
    #pragma unroll
    for (int i = 0; i < 4; i++) {
        int n = nt + 64 * i;
        float cs = __ldg(&g_colsum[n]);
        #pragma unroll
        for (int k = 0; k < 7; k++) {
            int p = pt * 7 + k;
            if (p < 27) {
                float raw = hsum2(acc[i][k]);
                bout[(size_t)p * NB + n] = (raw - mean_s[p] * cs) * inv_s[p];
            }
        }
    }
}

// ---------------- K3: fused LCA (all 50 iterations per CTA) ----------------
// one CTA per (image, patch-row) = 27 patches (+1 dummy). Thread: 4 bases x 7 patches.
#define K3_AS_F   (28 * NB)                  // a in smem, [28][256]
#define K3_GS_OFF (K3_AS_F * 4)              // 28672 B
#define K3_SMEM   (K3_GS_OFF + 256 * 33 * 8) // 96256 B (gram chunk [256 n][33 jpairs])

__global__ void __launch_bounds__(256, 1) lca_kernel() {
    extern __shared__ char smraw[];
    float* a_s = (float*)smraw;                 // [p 0..27][n 0..255]
    u64*   gs2 = (u64*)(smraw + K3_GS_OFF);     // [n][33] padded j-pairs

    const int blk = blockIdx.x;
    const int im  = blk / NROW;
    const int py  = blk - im * NROW;
    const int t   = threadIdx.x;
    const int pt  = t >> 6;
    const int nt  = t & 63;

    float u[4][7], brg[4][7];
    const float* bbase = g_b + (size_t)(im * NPATIMG + py * NROW) * NB;
    #pragma unroll
    for (int i = 0; i < 4; i++)
        #pragma unroll
        for (int k = 0; k < 7; k++) {
            int p = pt * 7 + k;
            brg[i][k] = (p < 27) ? bbase[(size_t)p * NB + nt + 64 * i] : 0.0f;
            u[i][k] = 0.0f;
        }

    const u64* G2 = (const u64*)g_gram;   // row = 128 u64

    for (int it = 0; it < ITERS; it++) {
        __syncthreads();   // prev-iter a_s readers done
        #pragma unroll
        for (int i = 0; i < 4; i++)
            #pragma unroll
            for (int k = 0; k < 7; k++) {
                int p = pt * 7 + k;        // includes dummy row 27 (stays zero)
                a_s[p * NB + nt + 64 * i] = softshrink(u[i][k]);
            }

        u64 acc[4][7];
        #pragma unroll
        for (int i = 0; i < 4; i++)
            #pragma unroll
            for (int k = 0; k < 7; k++) acc[i][k] = 0ull;

        #pragma unroll 1
        for (int j0 = 0; j0 < NB; j0 += 64) {
            __syncthreads();   // prev chunk consumers done
            #pragma unroll
            for (int r = 0; r < 32; r++) {
                int n = r * 8 + (t >> 5);
                gs2[n * 33 + (t & 31)] = __ldg(&G2[(size_t)n * 128 + (j0 >> 1) + (t & 31)]);
            }
            __syncthreads();

            #pragma unroll 4
            for (int q = 0; q < 32; q++) {
                u64 av[7];
                #pragma unroll
                for (int k = 0; k < 7; k++) {
                    int p = pt * 7 + k;
                    av[k] = *(const u64*)(a_s + p * NB + j0 + 2 * q);
                }
                #pragma unroll
                for (int i = 0; i < 4; i++) {
                    u64 g = gs2[(nt + 64 * i) * 33 + q];
                    #pragma unroll
                    for (int k = 0; k < 7; k++) fma2(acc[i][k], av[k], g);
                }
            }
        }

        // u += 0.01 * (b - u - a@gram)
        #pragma unroll
        for (int i = 0; i < 4; i++)
            #pragma unroll
            for (int k = 0; k < 7; k++) {
                float s = hsum2(acc[i][k]);
                u[i][k] += 0.01f * (brg[i][k] - u[i][k] - s);
            }
    }

    // epilogue: codes = softshrink(u); running max per (image, basis)
    #pragma unroll
    for (int i = 0; i < 4; i++) {
        float cm = -__int_as_float(0x7f800000);  // -inf
        #pragma unroll
        for (int k = 0; k < 7; k++) {
            int p = pt * 7 + k;
            if (p < 27) cm = fmaxf(cm, softshrink(u[i][k]));
        }
        atomicMax(&g_maxbits[im * NB + nt + 64 * i], enc_f(cm));
    }
}

// ---------------- K4: decode running max to output ----------------
__global__ void finalize_kernel(float* __restrict__ out) {
    int idx = blockIdx.x * NB + threadIdx.x;
    unsigned int k = g_maxbits[idx];
    out[idx] = (k & 0x80000000u) ? __uint_as_float(k & 0x7fffffffu)
                                 : __uint_as_float(~k);
}

// ---------------- launch ----------------
extern "C" void kernel_launch(void* const* d_in, const int* in_sizes, int n_in,
                              void* d_out, int out_size) {
    const float* image = (const float*)d_in[0];
    const float* dict  = (const float*)d_in[1];
    float* out = (float*)d_out;

    cudaFuncSetAttribute(b_kernel,   cudaFuncAttributeMaxDynamicSharedMemorySize, K2_SMEM);
    cudaFuncSetAttribute(lca_kernel, cudaFuncAttributeMaxDynamicSharedMemorySize, K3_SMEM);

    init_kernel<<<NIMG, NB>>>();
    gram_kernel<<<NB, 256>>>(dict);
    b_kernel<<<NIMG * NROW, 256, K2_SMEM>>>(image, dict);
    lca_kernel<<<NIMG * NROW, 256, K3_SMEM>>>();
    finalize_kernel<<<NIMG, NB>>>(out);
}

// round 4
// speedup vs baseline: 4.7196x; 4.7196x over previous
#include <cuda_runtime.h>
#include <cuda_bf16.h>
#include <cstdint>

// ---------------- problem constants ----------------
#define NB      256     // bases
#define KD      768     // patch dim (3*16*16)
#define NIMG    64
#define NROW    27      // patch rows (= cols) per image
#define NPATIMG 729     // 27*27
#define NPTOT   (NIMG * NPATIMG)   // 46656
#define ITERS   50

typedef unsigned long long u64;

// ---------------- device scratch (static: allocation-free) ----------------
__device__ float        g_gram[NB * NB];                 // D D^T - I (fp32)
__device__ float        g_colsum[NB];                    // row sums of D
__device__ float        g_b[(size_t)NPTOT * NB];         // feedforward drive (47.8 MB)
__device__ unsigned int g_maxbits[NIMG * NB];            // monotone-encoded running max

// ---------------- generic helpers ----------------
__device__ __forceinline__ void fma2(u64 &acc, u64 a, u64 b) {
    asm("fma.rn.f32x2 %0, %1, %2, %0;" : "+l"(acc) : "l"(a), "l"(b));
}
__device__ __forceinline__ float hsum2(u64 v) {
    unsigned int lo, hi;
    asm("mov.b64 {%0,%1}, %2;" : "=r"(lo), "=r"(hi) : "l"(v));
    return __uint_as_float(lo) + __uint_as_float(hi);
}
__device__ __forceinline__ float softshrink(float x) {
    return copysignf(fmaxf(fabsf(x) - 0.5f, 0.0f), x);
}
// softshrink(-0.01*x): the code/activation given register state r = -100*u
__device__ __forceinline__ float shneg(float x) {
    float t = fmaxf(fmaf(fabsf(x), 0.01f, -0.5f), 0.0f);
    return copysignf(t, -x);
}
__device__ __forceinline__ unsigned int enc_f(float x) {
    unsigned int b = __float_as_uint(x);
    return (b & 0x80000000u) ? ~b : (b | 0x80000000u);
}
__device__ __forceinline__ uint32_t bf2u(float a, float b) {
    __nv_bfloat162 h = __float22bfloat162_rn(make_float2(a, b));
    return *reinterpret_cast<uint32_t*>(&h);
}
// m16n8k16 row.col bf16 -> f32, D accumulated in place
__device__ __forceinline__ void mma16816(float d[4], uint32_t a0, uint32_t a1,
                                         uint32_t a2, uint32_t a3,
                                         uint32_t b0, uint32_t b1) {
    asm volatile(
        "mma.sync.aligned.m16n8k16.row.col.f32.bf16.bf16.f32 "
        "{%0,%1,%2,%3}, {%4,%5,%6,%7}, {%8,%9}, {%0,%1,%2,%3};"
        : "+f"(d[0]), "+f"(d[1]), "+f"(d[2]), "+f"(d[3])
        : "r"(a0), "r"(a1), "r"(a2), "r"(a3), "r"(b0), "r"(b1));
}

// ---------------- K0: init running max ----------------
__global__ void init_kernel() {
    g_maxbits[blockIdx.x * NB + threadIdx.x] = 0u;
}

// ---------------- K1: gram = D D^T - I, colsum ----------------
__global__ void __launch_bounds__(256) gram_kernel(const float* __restrict__ D) {
    __shared__ float di[KD];
    __shared__ float red[256];
    const int i = blockIdx.x;
    const int t = threadIdx.x;

    const float4* Di4 = (const float4*)(D + (size_t)i * KD);
    for (int q = t; q < KD / 4; q += 256) ((float4*)di)[q] = Di4[q];
    __syncthreads();

    const float4* Dj4 = (const float4*)(D + (size_t)t * KD);
    float acc = 0.f;
    #pragma unroll 4
    for (int q = 0; q < KD / 4; q++) {
        float4 v = __ldg(&Dj4[q]);
        acc += v.x * di[4*q] + v.y * di[4*q+1] + v.z * di[4*q+2] + v.w * di[4*q+3];
    }
    g_gram[i * NB + t] = acc - ((i == t) ? 1.0f : 0.0f);

    red[t] = di[t] + di[t + 256] + di[t + 512];
    __syncthreads();
    for (int o = 128; o > 0; o >>= 1) {
        if (t < o) red[t] += red[t + o];
        __syncthreads();
    }
    if (t == 0) g_colsum[i] = red[0];
}

// ---------------- K2: patch strip -> b = std_fold(raw @ D^T) ----------------
#define K2_STRIP_F   (3 * 16 * 224)
#define K2_DT2_OFF   43264
#define K2_SMEM      (K2_DT2_OFF + 32 * 256 * 8)

__global__ void __launch_bounds__(256, 1) b_kernel(const float* __restrict__ img,
                                                   const float* __restrict__ D) {
    extern __shared__ char smraw[];
    float* strip  = (float*)smraw;
    float* mean_s = strip + K2_STRIP_F;
    float* inv_s  = mean_s + 28;
    u64*   dt2    = (u64*)(smraw + K2_DT2_OFF);

    const int blk = blockIdx.x;
    const int im  = blk / NROW;
    const int py  = blk - im * NROW;
    const int t   = threadIdx.x;
    const int pt  = t >> 6;
    const int nt  = t & 63;

    const float* ibase = img + (size_t)im * 3 * 224 * 224 + (size_t)(py * 8) * 224;
    for (int e = t; e < K2_STRIP_F; e += 256) {
        int c   = e / 3584;
        int rem = e - c * 3584;
        strip[e] = ibase[(size_t)c * 224 * 224 + rem];
    }
    __syncthreads();

    {
        int p  = t >> 3; if (p > 26) p = 26;
        int l8 = t & 7;
        float sm = 0.f, sq = 0.f;
        int xoff = p * 8;
        for (int d = l8; d < KD; d += 8) {
            int rowi = d >> 4;
            int pw   = d & 15;
            float v = strip[rowi * 224 + xoff + pw];
            sm += v; sq += v * v;
        }
        #pragma unroll
        for (int o = 4; o > 0; o >>= 1) {
            sm += __shfl_down_sync(0xffffffffu, sm, o);
            sq += __shfl_down_sync(0xffffffffu, sq, o);
        }
        if (l8 == 0 && (t >> 3) < 27) {
            float m   = sm * (1.0f / 768.0f);
            float var = fmaxf(sq - sm * sm * (1.0f / 768.0f), 0.0f) * (1.0f / 767.0f);
            mean_s[p] = m;
            inv_s[p]  = 1.0f / (sqrtf(var) + 1e-8f);
        }
    }

    u64 acc[4][7];
    #pragma unroll
    for (int i = 0; i < 4; i++)
        #pragma unroll
        for (int k = 0; k < 7; k++) acc[i][k] = 0ull;

    const u64* Dg = (const u64*)D;
    #pragma unroll 1
    for (int d0 = 0; d0 < KD; d0 += 64) {
        __syncthreads();
        #pragma unroll
        for (int r = 0; r < 32; r++) {
            int n = r * 8 + (t >> 5);
            dt2[(size_t)(t & 31) * NB + n] = __ldg(&Dg[(size_t)n * 384 + (d0 >> 1) + (t & 31)]);
        }
        __syncthreads();

        #pragma unroll 4
        for (int q = 0; q < 32; q++) {
            int d    = d0 + 2 * q;
            int rowi = d >> 4;
            int pw   = d & 15;
            const float* srow = strip + rowi * 224 + pw;
            u64 av[7];
            #pragma unroll
            for (int k = 0; k < 7; k++) {
                int p  = pt * 7 + k;
                int px = (p > 26) ? 26 : p;
                av[k] = *(const u64*)(srow + px * 8);
            }
            #pragma unroll
            for (int i = 0; i < 4; i++) {
                u64 g = dt2[(size_t)q * NB + nt + 64 * i];
                #pragma unroll
                for (int k = 0; k < 7; k++) fma2(acc[i][k], av[k], g);
            }
        }
    }

    float* bout = g_b + (size_t)(im * NPATIMG + py * NROW) * NB;
    #pragma unroll
    for (int i = 0; i < 4; i++) {
        int n = nt + 64 * i;
        float cs = __ldg(&g_colsum[n]);
        #pragma unroll
        for (int k = 0; k < 7; k++) {
            int p = pt * 7 + k;
            if (p < 27) {
                float raw = hsum2(acc[i][k]);
                bout[(size_t)p * NB + n] = (raw - mean_s[p] * cs) * inv_s[p];
            }
        }
    }
}

// ---------------- K3: LCA via mma.sync (bf16), in-register chaining ----------------
// One warp = 16 patches x 256 bases, fully independent (no syncs in mainloop).
// Register state r = -100*u as 32 m16n8 D-fragments (128 f32/thread). Per iter:
//   a-frags (bf16) converted in-register from r (D-frag layout == A-frag layout),
//   r <- 0.99*r - b (accumulator re-init), then 512 HMMAs: r += a @ gram.
// gram lives in SMEM pre-fragmented in exact B-fragment order (128 KB, loaded once).
// Per-warp analytic warm start: while a==0, u_S = (1-0.99^S)*b exactly.
#define LCA_SMEM (131072 + 2048)
#define NPB ((NPTOT + 127) / 128)   // 365

__global__ void __launch_bounds__(256, 1) lca_mma_kernel() {
    extern __shared__ char smraw[];
    uint2*        bsm   = (uint2*)smraw;                 // [16384] prefragged gram
    unsigned int* stage = (unsigned int*)(smraw + 131072); // [2][256] per-CTA max

    const int tid  = threadIdx.x;
    const int w    = tid >> 5;
    const int lane = tid & 31;

    // zero the stage cells
    if (tid < 512) stage[tid] = 0u;   // 256 threads: handle 2 each below
    if (tid + 256 < 512) stage[tid + 256] = 0u;

    // pre-fragment gram (bf16) into B-fragment order:
    // entry e=(kk*32+j)*32+ln holds {g[k0][n],g[k0+1][n]} , {g[k0+8][n],g[k0+9][n]}
    // with k0 = 16*kk + 2*(ln&3), n = 8*j + (ln>>2)
    for (int e = tid; e < 16384; e += 256) {
        int kk = e >> 10;
        int j  = (e >> 5) & 31;
        int ln = e & 31;
        int k0 = kk * 16 + 2 * (ln & 3);
        int n  = j * 8 + (ln >> 2);
        uint32_t lo = bf2u(g_gram[k0 * NB + n],       g_gram[(k0 + 1) * NB + n]);
        uint32_t hi = bf2u(g_gram[(k0 + 8) * NB + n], g_gram[(k0 + 9) * NB + n]);
        bsm[e] = make_uint2(lo, hi);
    }
    __syncthreads();

    // ---- per-warp patch assignment ----
    const int base    = blockIdx.x * 128 + w * 16;
    const int row_lo  = lane >> 2;
    const int gpl     = base + row_lo;
    const int gph     = gpl + 8;
    const bool vl     = gpl < NPTOT;
    const bool vh     = gph < NPTOT;
    const float fl    = vl ? 1.0f : 0.0f;
    const float fh    = vh ? 1.0f : 0.0f;
    const float2* blf = (const float2*)(g_b + (size_t)(vl ? gpl : 0) * NB + 2 * (lane & 3));
    const float2* bhf = (const float2*)(g_b + (size_t)(vh ? gph : 0) * NB + 2 * (lane & 3));

    // ---- warm start: max |b| over the warp's 16x256 block ----
    float mx = 0.f;
    #pragma unroll
    for (int j = 0; j < 32; j++) {
        float2 x = __ldg(blf + 4 * j);
        float2 y = __ldg(bhf + 4 * j);
        mx = fmaxf(mx, fmaxf(fl * fmaxf(fabsf(x.x), fabsf(x.y)),
                             fh * fmaxf(fabsf(y.x), fabsf(y.y))));
    }
    float m1 = __uint_as_float(__reduce_max_sync(0xffffffffu, __float_as_uint(mx)));

    int S = 0; float gg = 1.0f;
    while (S < ITERS - 1 && (1.0f - gg) * m1 < 0.4999f) { S++; gg *= 0.99f; }
    const int   R = ITERS - S;           // remaining MMA iterations (>=1)
    const float f = -(1.0f - gg) * 100.0f;  // r_init = -100 * u_S = -100*f0*b

    // ---- init r = -100 * u_S ----
    float r[32][4];
    #pragma unroll
    for (int j = 0; j < 32; j++) {
        float2 x = __ldg(blf + 4 * j);
        float2 y = __ldg(bhf + 4 * j);
        r[j][0] = f * (x.x * fl);
        r[j][1] = f * (x.y * fl);
        r[j][2] = f * (y.x * fh);
        r[j][3] = f * (y.y * fh);
    }

    const uint2* bwl = bsm + lane;   // per-lane B-frag stream base

    // ---- mainloop: r <- (a @ gram)*100... kept as r' = 0.99 r - b + a@gram*... ----
    // invariant: u = -0.01*r. a = softshrink(u) = shneg(r).
    // C_init = 0.99*r - b ; after 512 MMAs r = a@gram + C_init => u_new = -0.01*r. OK.
    #pragma unroll 1
    for (int it = 0; it < R; it++) {
        // A fragments from current r (must complete before r is overwritten)
        uint32_t a[16][4];
        #pragma unroll
        for (int kk = 0; kk < 16; kk++) {
            a[kk][0] = bf2u(shneg(r[2*kk][0]),   shneg(r[2*kk][1]));
            a[kk][1] = bf2u(shneg(r[2*kk][2]),   shneg(r[2*kk][3]));
            a[kk][2] = bf2u(shneg(r[2*kk+1][0]), shneg(r[2*kk+1][1]));
            a[kk][3] = bf2u(shneg(r[2*kk+1][2]), shneg(r[2*kk+1][3]));
        }
        // accumulator re-init: r = 0.99*r - b
        #pragma unroll
        for (int j = 0; j < 32; j++) {
            float2 x = __ldg(blf + 4 * j);
            float2 y = __ldg(bhf + 4 * j);
            r[j][0] = fmaf(r[j][0], 0.99f, -(x.x * fl));
            r[j][1] = fmaf(r[j][1], 0.99f, -(x.y * fl));
            r[j][2] = fmaf(r[j][2], 0.99f, -(y.x * fh));
            r[j][3] = fmaf(r[j][3], 0.99f, -(y.y * fh));
        }
        // r += a @ gram   (512 HMMAs, B frags streamed from smem)
        #pragma unroll
        for (int kk = 0; kk < 16; kk++) {
            #pragma unroll
            for (int j = 0; j < 32; j++) {
                uint2 bb = bwl[(kk * 32 + j) * 32];
                mma16816(r[j], a[kk][0], a[kk][1], a[kk][2], a[kk][3], bb.x, bb.y);
            }
        }
    }

    // ---- epilogue: codes = softshrink(u) = shneg(r); per-CTA smem max stage ----
    const int im_base = (blockIdx.x * 128) / NPATIMG;
    const int iml = vl ? (gpl / NPATIMG - im_base) : 0;
    const int imh = vh ? (gph / NPATIMG - im_base) : 0;
    #pragma unroll
    for (int j = 0; j < 32; j++) {
        int n0 = 2 * (lane & 3) + 8 * j;
        if (vl) {
            atomicMax(&stage[iml * NB + n0],     enc_f(shneg(r[j][0])));
            atomicMax(&stage[iml * NB + n0 + 1], enc_f(shneg(r[j][1])));
        }
        if (vh) {
            atomicMax(&stage[imh * NB + n0],     enc_f(shneg(r[j][2])));
            atomicMax(&stage[imh * NB + n0 + 1], enc_f(shneg(r[j][3])));
        }
    }
    __syncthreads();

    const int last_p  = min(blockIdx.x * 128 + 127, NPTOT - 1);
    const int im_last = last_p / NPATIMG;
    #pragma unroll
    for (int c = tid; c < 512; c += 256) {
        int li = c >> 8, n = c & 255;
        int img = im_base + li;
        if (img <= im_last && stage[c])
            atomicMax(&g_maxbits[img * NB + n], stage[c]);
    }
}

// ---------------- K4: decode running max to output ----------------
__global__ void finalize_kernel(float* __restrict__ out) {
    int idx = blockIdx.x * NB + threadIdx.x;
    unsigned int k = g_maxbits[idx];
    out[idx] = (k & 0x80000000u) ? __uint_as_float(k & 0x7fffffffu)
                                 : __uint_as_float(~k);
}

// ---------------- launch ----------------
extern "C" void kernel_launch(void* const* d_in, const int* in_sizes, int n_in,
                              void* d_out, int out_size) {
    const float* image = (const float*)d_in[0];
    const float* dict  = (const float*)d_in[1];
    float* out = (float*)d_out;

    cudaFuncSetAttribute(b_kernel,       cudaFuncAttributeMaxDynamicSharedMemorySize, K2_SMEM);
    cudaFuncSetAttribute(lca_mma_kernel, cudaFuncAttributeMaxDynamicSharedMemorySize, LCA_SMEM);

    init_kernel<<<NIMG, NB>>>();
    gram_kernel<<<NB, 256>>>(dict);
    b_kernel<<<NIMG * NROW, 256, K2_SMEM>>>(image, dict);
    lca_mma_kernel<<<NPB, 256, LCA_SMEM>>>();
    finalize_kernel<<<NIMG, NB>>>(out);
}

// round 5
// speedup vs baseline: 9.2755x; 1.9653x over previous
#include <cuda_runtime.h>
#include <cuda_bf16.h>
#include <cstdint>

// ---------------- problem constants ----------------
#define NB      256     // bases
#define KD      768     // patch dim (3*16*16)
#define NIMG    64
#define NROW    27      // patch rows (= cols) per image
#define NPATIMG 729     // 27*27
#define NPTOT   (NIMG * NPATIMG)   // 46656
#define ITERS   50

typedef unsigned long long u64;

// ---------------- device scratch (static: allocation-free) ----------------
__device__ float        g_gram[NB * NB];                 // D D^T - I (fp32)
__device__ float        g_b[(size_t)NPTOT * NB];         // feedforward drive (47.8 MB)
__device__ unsigned int g_maxbits[NIMG * NB];            // monotone-encoded running max
__device__ uint4        g_dfrag[48 * 32 * 32];           // D in B-frag order, hi/lo bf16 (786KB)

// ---------------- generic helpers ----------------
__device__ __forceinline__ float softshrink(float x) {
    return copysignf(fmaxf(fabsf(x) - 0.5f, 0.0f), x);
}
// softshrink(-0.01*x): the code/activation given register state r = -100*u
__device__ __forceinline__ float shneg(float x) {
    float t = fmaxf(fmaf(fabsf(x), 0.01f, -0.5f), 0.0f);
    return copysignf(t, -x);
}
__device__ __forceinline__ unsigned int enc_f(float x) {
    unsigned int b = __float_as_uint(x);
    return (b & 0x80000000u) ? ~b : (b | 0x80000000u);
}
__device__ __forceinline__ uint32_t bf2u(float a, float b) {
    __nv_bfloat162 h = __float22bfloat162_rn(make_float2(a, b));
    return *reinterpret_cast<uint32_t*>(&h);
}
__device__ __forceinline__ float bfh(float v) {
    return __bfloat162float(__float2bfloat16_rn(v));
}
// m16n8k16 row.col bf16 -> f32, D accumulated in place
__device__ __forceinline__ void mma16816(float d[4], uint32_t a0, uint32_t a1,
                                         uint32_t a2, uint32_t a3,
                                         uint32_t b0, uint32_t b1) {
    asm volatile(
        "mma.sync.aligned.m16n8k16.row.col.f32.bf16.bf16.f32 "
        "{%0,%1,%2,%3}, {%4,%5,%6,%7}, {%8,%9}, {%0,%1,%2,%3};"
        : "+f"(d[0]), "+f"(d[1]), "+f"(d[2]), "+f"(d[3])
        : "r"(a0), "r"(a1), "r"(a2), "r"(a3), "r"(b0), "r"(b1));
}

// ---------------- K0: init running max ----------------
__global__ void init_kernel() {
    g_maxbits[blockIdx.x * NB + threadIdx.x] = 0u;
}

// ---------------- K1: gram = D D^T - I ----------------
__global__ void __launch_bounds__(256) gram_kernel(const float* __restrict__ D) {
    __shared__ float di[KD];
    const int i = blockIdx.x;
    const int t = threadIdx.x;

    const float4* Di4 = (const float4*)(D + (size_t)i * KD);
    for (int q = t; q < KD / 4; q += 256) ((float4*)di)[q] = Di4[q];
    __syncthreads();

    const float4* Dj4 = (const float4*)(D + (size_t)t * KD);
    float acc = 0.f;
    #pragma unroll 4
    for (int q = 0; q < KD / 4; q++) {
        float4 v = __ldg(&Dj4[q]);
        acc += v.x * di[4*q] + v.y * di[4*q+1] + v.z * di[4*q+2] + v.w * di[4*q+3];
    }
    g_gram[i * NB + t] = acc - ((i == t) ? 1.0f : 0.0f);
}

// ---------------- K1b: pre-fragment D (hi/lo bf16) into B-frag order ----------------
// entry e = (kk*32 + j)*32 + ln : k0 = kk*16 + 2*(ln&3), n = j*8 + (ln>>2)
// uint4 = { hi{D[n][k0],D[n][k0+1]}, hi{D[n][k0+8],D[n][k0+9]}, lo{...}, lo{...} }
__global__ void __launch_bounds__(256) dfrag_kernel(const float* __restrict__ D) {
    int e = blockIdx.x * 256 + threadIdx.x;       // grid 192 -> 49152
    int kk = e >> 10;
    int j  = (e >> 5) & 31;
    int ln = e & 31;
    int k0 = kk * 16 + 2 * (ln & 3);
    int n  = j * 8 + (ln >> 2);
    const float* Dr = D + (size_t)n * KD;
    float v00 = __ldg(Dr + k0),     v01 = __ldg(Dr + k0 + 1);
    float v08 = __ldg(Dr + k0 + 8), v09 = __ldg(Dr + k0 + 9);
    uint4 q;
    q.x = bf2u(v00, v01);
    q.y = bf2u(v08, v09);
    q.z = bf2u(v00 - bfh(v00), v01 - bfh(v01));
    q.w = bf2u(v08 - bfh(v08), v09 - bfh(v09));
    g_dfrag[e] = q;
}

// ---------------- K2: b = standardized_patches @ D^T via mma (hi/lo split) ----------------
// One CTA = one image x 4 patch rows (108 patches, M=128 padded). 512 threads,
// warp grid 4M x 4N (warp tile 32x64). Standardization folded into A at build.
#define BSM_STAT  107520                     // strip = 3*40*224 floats before this
#define BSM_A     108544                     // A chunk: [128][66] f32 = 33792 B
#define BSM_B     142336                     // B chunk: [4][32][32] uint4 = 65536 B
#define B2_SMEM   (BSM_B + 65536)            // 207872 B

__global__ void __launch_bounds__(512, 1) b_mma_kernel(const float* __restrict__ img) {
    extern __shared__ char sm[];
    float* strip  = (float*)sm;                    // [3][40][224]
    float* mean_s = (float*)(sm + BSM_STAT);       // [128]
    float* inv_s  = mean_s + 128;
    float* Asm    = (float*)(sm + BSM_A);          // [128][66]
    uint4* Bsm    = (uint4*)(sm + BSM_B);          // [4*32*32]

    const int blk  = blockIdx.x;
    const int im   = blk / 7;
    const int band = blk - im * 7;
    const int py0  = band * 4;
    const int nr   = (band == 6) ? 3 : 4;
    const int npat = 27 * nr;
    const int srows = 8 * nr + 8;
    const int t = threadIdx.x;

    // ---- load strip ----
    const float* ib = img + (size_t)im * 3 * 224 * 224 + (size_t)(py0 * 8) * 224;
    const int tot = 3 * srows * 224;
    for (int e = t; e < tot; e += 512) {
        int c   = e / (srows * 224);
        int rem = e - c * (srows * 224);
        strip[(c * 40) * 224 + rem] = ib[(size_t)c * 224 * 224 + rem];
    }
    __syncthreads();

    // ---- per-patch stats: 4 lanes per patch ----
    {
        int p0 = t >> 2;
        int p  = (p0 < npat) ? p0 : (npat - 1);
        int l4 = t & 3;
        int pr = p / 27, pc = p - pr * 27;
        int y0 = pr * 8, x0 = pc * 8;
        float sm_ = 0.f, sq = 0.f;
        for (int d = l4; d < KD; d += 4) {
            int c   = d >> 8;
            int r16 = (d >> 4) & 15;
            int pw  = d & 15;
            float v = strip[(c * 40 + y0 + r16) * 224 + x0 + pw];
            sm_ += v; sq += v * v;
        }
        sm_ += __shfl_down_sync(0xffffffffu, sm_, 2);
        sq  += __shfl_down_sync(0xffffffffu, sq,  2);
        sm_ += __shfl_down_sync(0xffffffffu, sm_, 1);
        sq  += __shfl_down_sync(0xffffffffu, sq,  1);
        if (l4 == 0 && p0 < npat) {
            float m   = sm_ * (1.0f / 768.0f);
            float var = fmaxf(sq - sm_ * sm_ * (1.0f / 768.0f), 0.0f) * (1.0f / 767.0f);
            mean_s[p0] = m;
            inv_s[p0]  = 1.0f / (sqrtf(var) + 1e-8f);
        }
    }

    const int w    = t >> 5;
    const int lane = t & 31;
    const int wm   = w & 3;        // m-group: rows [wm*32, wm*32+32)
    const int wn   = w >> 2;       // n-group: j tiles [wn*8, wn*8+8)
    const int row  = lane >> 2;
    const int kp   = 2 * (lane & 3);

    float acc[2][8][4];
    #pragma unroll
    for (int mt = 0; mt < 2; mt++)
        #pragma unroll
        for (int j = 0; j < 8; j++)
            #pragma unroll
            for (int c = 0; c < 4; c++) acc[mt][j][c] = 0.f;

    // thread's A-staging identity
    const int  am  = t >> 2;
    const bool amv = am < npat;
    const int  apr = amv ? am / 27 : 0;
    const int  apc = amv ? (am - apr * 27) : 0;

    __syncthreads();   // stats visible

    const float amm = amv ? mean_s[am] : 0.f;
    const float aiv = amv ? inv_s[am]  : 0.f;

    // ---- main k loop: 12 chunks of 64 ----
    #pragma unroll 1
    for (int ch = 0; ch < 12; ch++) {
        // stage A chunk (standardized fp32), [128][66]
        const int kc0 = ch * 64;
        #pragma unroll
        for (int i = 0; i < 16; i++) {
            int kl = (t & 3) * 16 + i;
            int d  = kc0 + kl;
            int c   = d >> 8;
            int r16 = (d >> 4) & 15;
            int pw  = d & 15;
            float v = amv ? strip[(c * 40 + apr * 8 + r16) * 224 + apc * 8 + pw] : 0.f;
            Asm[am * 66 + kl] = (v - amm) * aiv;
        }
        // stage B chunk (64KB contiguous)
        const uint4* gsrc = g_dfrag + (size_t)ch * 4096;
        #pragma unroll
        for (int e = t; e < 4096; e += 512) Bsm[e] = __ldg(&gsrc[e]);
        __syncthreads();

        #pragma unroll
        for (int kkl = 0; kkl < 4; kkl++) {
            const int kt = kkl * 16;
            uint32_t ah[2][4], al[2][4];
            #pragma unroll
            for (int mt = 0; mt < 2; mt++) {
                int mrow = wm * 32 + mt * 16 + row;
                float2 v0 = *(const float2*)&Asm[mrow * 66 + kt + kp];
                float2 v1 = *(const float2*)&Asm[(mrow + 8) * 66 + kt + kp];
                float2 v2 = *(const float2*)&Asm[mrow * 66 + kt + kp + 8];
                float2 v3 = *(const float2*)&Asm[(mrow + 8) * 66 + kt + kp + 8];
                ah[mt][0] = bf2u(v0.x, v0.y);
                ah[mt][1] = bf2u(v1.x, v1.y);
                ah[mt][2] = bf2u(v2.x, v2.y);
                ah[mt][3] = bf2u(v3.x, v3.y);
                al[mt][0] = bf2u(v0.x - bfh(v0.x), v0.y - bfh(v0.y));
                al[mt][1] = bf2u(v1.x - bfh(v1.x), v1.y - bfh(v1.y));
                al[mt][2] = bf2u(v2.x - bfh(v2.x), v2.y - bfh(v2.y));
                al[mt][3] = bf2u(v3.x - bfh(v3.x), v3.y - bfh(v3.y));
            }
            #pragma unroll
            for (int j = 0; j < 8; j++) {
                uint4 q = Bsm[(kkl * 32 + wn * 8 + j) * 32 + lane];
                #pragma unroll
                for (int mt = 0; mt < 2; mt++) {
                    mma16816(acc[mt][j], ah[mt][0], ah[mt][1], ah[mt][2], ah[mt][3], q.x, q.y);
                    mma16816(acc[mt][j], ah[mt][0], ah[mt][1], ah[mt][2], ah[mt][3], q.z, q.w);
                    mma16816(acc[mt][j], al[mt][0], al[mt][1], al[mt][2], al[mt][3], q.x, q.y);
                }
            }
        }
        __syncthreads();   // before restaging
    }

    // ---- epilogue: write b ----
    const int pbase = (im * NROW + py0) * NROW;   // first patch of band
    #pragma unroll
    for (int mt = 0; mt < 2; mt++) {
        int m0 = wm * 32 + mt * 16 + row;
        int m1 = m0 + 8;
        #pragma unroll
        for (int j = 0; j < 8; j++) {
            int n0 = wn * 64 + j * 8 + kp;
            if (m0 < npat) {
                int gp = pbase + (m0 / 27) * NROW + (m0 % 27);
                *(float2*)(g_b + (size_t)gp * NB + n0) = make_float2(acc[mt][j][0], acc[mt][j][1]);
            }
            if (m1 < npat) {
                int gp = pbase + (m1 / 27) * NROW + (m1 % 27);
                *(float2*)(g_b + (size_t)gp * NB + n0) = make_float2(acc[mt][j][2], acc[mt][j][3]);
            }
        }
    }
}

// ---------------- K3: LCA via mma.sync (bf16), in-register chaining ----------------
// One warp = 16 patches x 256 bases, no syncs in mainloop. B-frags for (j, j+16)
// paired in one uint4 -> LDS.128 (half the LDS instruction count of round 4).
#define LCA_SMEM (131072 + 2048)
#define NPB ((NPTOT + 127) / 128)   // 365

__global__ void __launch_bounds__(256, 1) lca_mma_kernel() {
    extern __shared__ char smraw[];
    uint4*        bsm4  = (uint4*)smraw;                   // [8192] paired gram frags
    unsigned int* stage = (unsigned int*)(smraw + 131072); // [2][256] per-CTA max

    const int tid  = threadIdx.x;
    const int w    = tid >> 5;
    const int lane = tid & 31;

    if (tid < 256) { stage[tid] = 0u; stage[tid + 256] = 0u; }

    // pre-fragment gram (bf16) paired: entry (kk*16 + j)*32 + ln holds frags for
    // n-tiles j and j+16:  k0 = kk*16 + 2(ln&3), n1 = j*8 + (ln>>2), n2 = n1 + 128
    for (int e = tid; e < 8192; e += 256) {
        int kk = e >> 9;
        int j  = (e >> 5) & 15;
        int ln = e & 31;
        int k0 = kk * 16 + 2 * (ln & 3);
        int n1 = j * 8 + (ln >> 2);
        int n2 = n1 + 128;
        uint4 q;
        q.x = bf2u(g_gram[k0 * NB + n1],       g_gram[(k0 + 1) * NB + n1]);
        q.y = bf2u(g_gram[(k0 + 8) * NB + n1], g_gram[(k0 + 9) * NB + n1]);
        q.z = bf2u(g_gram[k0 * NB + n2],       g_gram[(k0 + 1) * NB + n2]);
        q.w = bf2u(g_gram[(k0 + 8) * NB + n2], g_gram[(k0 + 9) * NB + n2]);
        bsm4[e] = q;
    }
    __syncthreads();

    // ---- per-warp patch assignment ----
    const int base    = blockIdx.x * 128 + w * 16;
    const int row_lo  = lane >> 2;
    const int gpl     = base + row_lo;
    const int gph     = gpl + 8;
    const bool vl     = gpl < NPTOT;
    const bool vh     = gph < NPTOT;
    const float fl    = vl ? 1.0f : 0.0f;
    const float fh    = vh ? 1.0f : 0.0f;
    const float2* blf = (const float2*)(g_b + (size_t)(vl ? gpl : 0) * NB + 2 * (lane & 3));
    const float2* bhf = (const float2*)(g_b + (size_t)(vh ? gph : 0) * NB + 2 * (lane & 3));

    // ---- warm start: max |b| over the warp's 16x256 block ----
    float mx = 0.f;
    #pragma unroll
    for (int j = 0; j < 32; j++) {
        float2 x = __ldg(blf + 4 * j);
        float2 y = __ldg(bhf + 4 * j);
        mx = fmaxf(mx, fmaxf(fl * fmaxf(fabsf(x.x), fabsf(x.y)),
                             fh * fmaxf(fabsf(y.x), fabsf(y.y))));
    }
    float m1 = __uint_as_float(__reduce_max_sync(0xffffffffu, __float_as_uint(mx)));

    int S = 0; float gg = 1.0f;
    while (S < ITERS - 1 && (1.0f - gg) * m1 < 0.4999f) { S++; gg *= 0.99f; }
    const int   R = ITERS - S;
    const float f = -(1.0f - gg) * 100.0f;   // r = -100 * u

    float r[32][4];
    #pragma unroll
    for (int j = 0; j < 32; j++) {
        float2 x = __ldg(blf + 4 * j);
        float2 y = __ldg(bhf + 4 * j);
        r[j][0] = f * (x.x * fl);
        r[j][1] = f * (x.y * fl);
        r[j][2] = f * (y.x * fh);
        r[j][3] = f * (y.y * fh);
    }

    const uint4* bwl = bsm4 + lane;

    #pragma unroll 1
    for (int it = 0; it < R; it++) {
        uint32_t a[16][4];
        #pragma unroll
        for (int kk = 0; kk < 16; kk++) {
            a[kk][0] = bf2u(shneg(r[2*kk][0]),   shneg(r[2*kk][1]));
            a[kk][1] = bf2u(shneg(r[2*kk][2]),   shneg(r[2*kk][3]));
            a[kk][2] = bf2u(shneg(r[2*kk+1][0]), shneg(r[2*kk+1][1]));
            a[kk][3] = bf2u(shneg(r[2*kk+1][2]), shneg(r[2*kk+1][3]));
        }
        #pragma unroll
        for (int j = 0; j < 32; j++) {
            float2 x = __ldg(blf + 4 * j);
            float2 y = __ldg(bhf + 4 * j);
            r[j][0] = fmaf(r[j][0], 0.99f, -(x.x * fl));
            r[j][1] = fmaf(r[j][1], 0.99f, -(x.y * fl));
            r[j][2] = fmaf(r[j][2], 0.99f, -(y.x * fh));
            r[j][3] = fmaf(r[j][3], 0.99f, -(y.y * fh));
        }
        #pragma unroll
        for (int kk = 0; kk < 16; kk++) {
            #pragma unroll
            for (int j = 0; j < 16; j++) {
                uint4 q = bwl[(kk * 16 + j) * 32];
                mma16816(r[j],      a[kk][0], a[kk][1], a[kk][2], a[kk][3], q.x, q.y);
                mma16816(r[j + 16], a[kk][0], a[kk][1], a[kk][2], a[kk][3], q.z, q.w);
            }
        }
    }

    // ---- epilogue: per-CTA smem max stage, then global ----
    const int im_base = (blockIdx.x * 128) / NPATIMG;
    const int iml = vl ? (gpl / NPATIMG - im_base) : 0;
    const int imh = vh ? (gph / NPATIMG - im_base) : 0;
    #pragma unroll
    for (int j = 0; j < 32; j++) {
        int n0 = 2 * (lane & 3) + 8 * j;
        if (vl) {
            atomicMax(&stage[iml * NB + n0],     enc_f(shneg(r[j][0])));
            atomicMax(&stage[iml * NB + n0 + 1], enc_f(shneg(r[j][1])));
        }
        if (vh) {
            atomicMax(&stage[imh * NB + n0],     enc_f(shneg(r[j][2])));
            atomicMax(&stage[imh * NB + n0 + 1], enc_f(shneg(r[j][3])));
        }
    }
    __syncthreads();

    const int last_p  = min(blockIdx.x * 128 + 127, NPTOT - 1);
    const int im_last = last_p / NPATIMG;
    #pragma unroll
    for (int c = tid; c < 512; c += 256) {
        int li = c >> 8, n = c & 255;
        int img = im_base + li;
        if (img <= im_last && stage[c])
            atomicMax(&g_maxbits[img * NB + n], stage[c]);
    }
}

// ---------------- K4: decode running max to output ----------------
__global__ void finalize_kernel(float* __restrict__ out) {
    int idx = blockIdx.x * NB + threadIdx.x;
    unsigned int k = g_maxbits[idx];
    out[idx] = (k & 0x80000000u) ? __uint_as_float(k & 0x7fffffffu)
                                 : __uint_as_float(~k);
}

// ---------------- launch ----------------
extern "C" void kernel_launch(void* const* d_in, const int* in_sizes, int n_in,
                              void* d_out, int out_size) {
    const float* image = (const float*)d_in[0];
    const float* dict  = (const float*)d_in[1];
    float* out = (float*)d_out;

    cudaFuncSetAttribute(b_mma_kernel,   cudaFuncAttributeMaxDynamicSharedMemorySize, B2_SMEM);
    cudaFuncSetAttribute(lca_mma_kernel, cudaFuncAttributeMaxDynamicSharedMemorySize, LCA_SMEM);

    init_kernel<<<NIMG, NB>>>();
    gram_kernel<<<NB, 256>>>(dict);
    dfrag_kernel<<<192, 256>>>(dict);
    b_mma_kernel<<<NIMG * 7, 512, B2_SMEM>>>(image);
    lca_mma_kernel<<<NPB, 256, LCA_SMEM>>>();
    finalize_kernel<<<NIMG, NB>>>(out);
}